// round 2
// baseline (speedup 1.0000x reference)
#include <cuda_runtime.h>

#define DEVINL __device__ __forceinline__

DEVINL float ex2f_fast(float x) {
    float r; asm("ex2.approx.f32 %0, %1;" : "=f"(r) : "f"(x)); return r;
}
DEVINL float rcpf_fast(float x) {
    float r; asm("rcp.approx.f32 %0, %1;" : "=f"(r) : "f"(x)); return r;
}

// tanh(z) = 1 - 2/(exp(2z)+1), via EX2 (few-ulp) + RCP (1 ulp).
// NOT tanh.approx: its ~2^-10 abs error would feed the 128-step recurrence;
// this form keeps the carried state accurate to ~1e-6 (measured rel_err 1.3e-7).
DEVINL float tanh_acc(float z) {
    float e = ex2f_fast(2.8853900817779268f * z);   // 2*log2(e)
    return fmaf(-2.0f, rcpf_fast(e + 1.0f), 1.0f);
}

// sigmoid(10h) = 1/(1 + exp(-10h))
DEVINL float sig10(float h) {
    float e = ex2f_fast(-14.426950408889634f * h);  // -10*log2(e)
    return rcpf_fast(e + 1.0f);
}

__global__ void __launch_bounds__(128)
rnn_scan_kernel(const float4* __restrict__ x,     // (T, npairs) of float4 = 2 batch elems
                const float4* __restrict__ h0,
                const float* __restrict__ Wih,
                const float* __restrict__ Whh,
                const float* __restrict__ bih,
                const float* __restrict__ bhh,
                float4* __restrict__ out,
                float4* __restrict__ hid,
                int npairs, int T)
{
    int p = blockIdx.x * blockDim.x + threadIdx.x;
    if (p >= npairs) return;

    // 2x2 weights + fused bias (L1-cached broadcast loads)
    const float w00 = Wih[0], w01 = Wih[1], w10 = Wih[2], w11 = Wih[3];
    const float v00 = Whh[0], v01 = Whh[1], v10 = Whh[2], v11 = Whh[3];
    const float c0 = bih[0] + bhh[0], c1 = bih[1] + bhh[1];

    float4 h = h0[p];                  // (h0_a, h1_a, h0_b, h1_b)
    const float4* xp = x + p;
    float4*       op = out + p;

    #pragma unroll 4
    for (int t = 0; t < T; t++) {
        float4 xv = __ldcs(xp); xp += npairs;   // streaming: no reuse, evict-first

        float a0 = fmaf(w00, xv.x, fmaf(w01, xv.y, fmaf(v00, h.x, fmaf(v01, h.y, c0))));
        float a1 = fmaf(w10, xv.x, fmaf(w11, xv.y, fmaf(v10, h.x, fmaf(v11, h.y, c1))));
        float b0 = fmaf(w00, xv.z, fmaf(w01, xv.w, fmaf(v00, h.z, fmaf(v01, h.w, c0))));
        float b1 = fmaf(w10, xv.z, fmaf(w11, xv.w, fmaf(v10, h.z, fmaf(v11, h.w, c1))));

        h.x = tanh_acc(a0);
        h.y = tanh_acc(a1);
        h.z = tanh_acc(b0);
        h.w = tanh_acc(b1);

        float4 o;
        o.x = sig10(h.x);
        o.y = sig10(h.y);
        o.z = sig10(h.z);
        o.w = sig10(h.w);
        __stcs(op, o); op += npairs;            // streaming store
    }

    hid[p] = h;
}

extern "C" void kernel_launch(void* const* d_in, const int* in_sizes, int n_in,
                              void* d_out, int out_size)
{
    const float* x   = (const float*)d_in[0];
    const float* h   = (const float*)d_in[1];
    const float* Wih = (const float*)d_in[2];
    const float* Whh = (const float*)d_in[3];
    const float* bih = (const float*)d_in[4];
    const float* bhh = (const float*)d_in[5];

    const int B      = in_sizes[1] / 2;          // h is (1, B, 2)
    const int T      = in_sizes[0] / (B * 2);    // x is (T, B, 2)
    const int npairs = B / 2;                    // one thread = 2 batch elems (float4)

    float* out = (float*)d_out;                  // (T, B, 2) first
    float* hid = out + (size_t)in_sizes[0];      // then (1, B, 2)

    // 128-thread blocks -> grid 1024 on 148 SMs: max 7 vs mean 6.92 CTAs/SM
    // (1.2% imbalance) instead of 4 vs 3.46 (15%) with 256-thread blocks.
    const int threads = 128;
    const int blocks  = (npairs + threads - 1) / threads;
    rnn_scan_kernel<<<blocks, threads>>>(
        (const float4*)x, (const float4*)h,
        Wih, Whh, bih, bhh,
        (float4*)out, (float4*)hid,
        npairs, T);
}

// round 3
// speedup vs baseline: 1.2964x; 1.2964x over previous
#include <cuda_runtime.h>

#define DEVINL __device__ __forceinline__

DEVINL float ex2f_fast(float x) {
    float r; asm("ex2.approx.f32 %0, %1;" : "=f"(r) : "f"(x)); return r;
}
DEVINL float rcpf_fast(float x) {
    float r; asm("rcp.approx.f32 %0, %1;" : "=f"(r) : "f"(x)); return r;
}

// tanh(z) = 1 - 2/(exp(2z)+1), via EX2 (few-ulp) + RCP (1 ulp).
// NOT tanh.approx: its ~2^-10 abs error would feed the 128-step recurrence;
// this form keeps carried state accurate to ~1e-6 (measured rel_err 1.3e-7).
DEVINL float tanh_acc(float z) {
    float e = ex2f_fast(2.8853900817779268f * z);   // 2*log2(e)
    return fmaf(-2.0f, rcpf_fast(e + 1.0f), 1.0f);
}

// sigmoid(10h) = 1/(1 + exp(-10h))
DEVINL float sig10(float h) {
    float e = ex2f_fast(-14.426950408889634f * h);  // -10*log2(e)
    return rcpf_fast(e + 1.0f);
}

__global__ void __launch_bounds__(128)
rnn_scan_kernel(const float4* __restrict__ x,     // (T, npairs) of float4 = 2 batch elems
                const float4* __restrict__ h0,
                const float* __restrict__ Wih,
                const float* __restrict__ Whh,
                const float* __restrict__ bih,
                const float* __restrict__ bhh,
                float4* __restrict__ out,
                float4* __restrict__ hid,
                int npairs, int T)
{
    int p = blockIdx.x * blockDim.x + threadIdx.x;
    if (p >= npairs) return;

    // 2x2 weights + fused bias (L1-cached broadcast loads)
    const float w00 = Wih[0], w01 = Wih[1], w10 = Wih[2], w11 = Wih[3];
    const float v00 = Whh[0], v01 = Whh[1], v10 = Whh[2], v11 = Whh[3];
    const float c0 = bih[0] + bhh[0], c1 = bih[1] + bhh[1];

    float4 h = h0[p];                  // (h0_a, h1_a, h0_b, h1_b)
    const float4* xp = x + p;
    float4*       op = out + p;

    // Structural 4-deep load batching: all 4 LDG.E.128 issue before the
    // dependent tanh chains, guaranteeing MLP=4 per warp independent of
    // ptxas scheduling (the R2 regression lost this hoist).
    for (int t = 0; t < T; t += 4) {
        float4 buf[4];
        #pragma unroll
        for (int u = 0; u < 4; u++)
            buf[u] = __ldg(xp + (size_t)u * npairs);
        xp += (size_t)4 * npairs;

        #pragma unroll
        for (int u = 0; u < 4; u++) {
            float4 xv = buf[u];
            float a0 = fmaf(w00, xv.x, fmaf(w01, xv.y, fmaf(v00, h.x, fmaf(v01, h.y, c0))));
            float a1 = fmaf(w10, xv.x, fmaf(w11, xv.y, fmaf(v10, h.x, fmaf(v11, h.y, c1))));
            float b0 = fmaf(w00, xv.z, fmaf(w01, xv.w, fmaf(v00, h.z, fmaf(v01, h.w, c0))));
            float b1 = fmaf(w10, xv.z, fmaf(w11, xv.w, fmaf(v10, h.z, fmaf(v11, h.w, c1))));

            h.x = tanh_acc(a0);
            h.y = tanh_acc(a1);
            h.z = tanh_acc(b0);
            h.w = tanh_acc(b1);

            float4 o;
            o.x = sig10(h.x);
            o.y = sig10(h.y);
            o.z = sig10(h.z);
            o.w = sig10(h.w);
            op[(size_t)u * npairs] = o;
        }
        op += (size_t)4 * npairs;
    }

    hid[p] = h;
}

extern "C" void kernel_launch(void* const* d_in, const int* in_sizes, int n_in,
                              void* d_out, int out_size)
{
    const float* x   = (const float*)d_in[0];
    const float* h   = (const float*)d_in[1];
    const float* Wih = (const float*)d_in[2];
    const float* Whh = (const float*)d_in[3];
    const float* bih = (const float*)d_in[4];
    const float* bhh = (const float*)d_in[5];

    const int B      = in_sizes[1] / 2;          // h is (1, B, 2)
    const int T      = in_sizes[0] / (B * 2);    // x is (T, B, 2)
    const int npairs = B / 2;                    // one thread = 2 batch elems (float4)

    float* out = (float*)d_out;                  // (T, B, 2) first
    float* hid = out + (size_t)in_sizes[0];      // then (1, B, 2)

    // 128-thread blocks -> grid 1024 on 148 SMs: max 7 vs mean 6.92 CTAs/SM
    // (~1% imbalance) instead of 4 vs 3.46 (15%) with 256-thread blocks.
    const int threads = 128;
    const int blocks  = (npairs + threads - 1) / threads;
    rnn_scan_kernel<<<blocks, threads>>>(
        (const float4*)x, (const float4*)h,
        Wih, Whh, bih, bhh,
        (float4*)out, (float4*)hid,
        npairs, T);
}